// round 12
// baseline (speedup 1.0000x reference)
#include <cuda_runtime.h>
#include <cstdint>

#define H_DIM 512
#define W_DIM 512
#define CIN   3
#define COUT  32
#define NB    16
#define HW    (H_DIM * W_DIM)

#define NTHREADS 128
// smem x-tile layout: xs[c*824 + r*136 + s], c<3, r<6, s<130
#define RSTRIDE 136
#define CSTRIDE 824
#define XS_FLOATS 2496

// output staging buffer: per warp, 32 channels x 32 px, stride 36 (conflict-free)
#define BUFW 36
#define BUF_PER_WARP (32 * BUFW)   // 1152 floats

// Prepped B matrix: g_wB[k*32 + o] = tf32(Weff[o][PERM[k]]), 0 for pad taps
__device__ uint32_t g_wB[32 * 32];

// k -> tap id (c*9+i*3+j); -1 = pad (weight forced to 0).
__device__ __constant__ int c_PERM[32] = {
    0, 3, 6, 9,   12, 15, 18, 21,
    1, 4, 7, 10,  13, 16, 19, 22,
    2, 5, 8, 11,  14, 17, 20, 23,
    24, 25, 26, -1,  -1, -1, -1, -1
};

// smem float-offset for each k (c*824 + i*136 + j).
// Pad taps -> offset 0 (their B weight is exactly 0.0f; tile data is finite).
__device__ __constant__ int c_OFFS[32] = {
    0, 136, 272, 824,    960, 1096, 1648, 1784,
    1, 137, 273, 825,    961, 1097, 1649, 1785,
    2, 138, 274, 826,    962, 1098, 1650, 1786,
    1920, 1921, 1922, 0,  0, 0, 0, 0
};

__device__ __forceinline__ uint32_t cvt_tf32(float f) {
    uint32_t u;
    asm("cvt.rna.tf32.f32 %0, %1;" : "=r"(u) : "f"(f));
    return u;
}

// ---- one-time weight prep ----
__global__ void prep_weights_kernel(const float* __restrict__ Wm)
{
    const int s = blockIdx.x * blockDim.x + threadIdx.x;
    if (s >= 32 * 32) return;
    const int k = s / 32;
    const int o = s % 32;
    const int tap = c_PERM[k];
    float wv = 0.f;
    if (tap >= 0) {
        const int c  = tap / 9;
        const int ij = tap % 9;
        // COORDS order for ij=(i*3+j): (0,0),(1,0),(2,0),(0,1),(2,1),(0,2),(1,2),(2,2)
        const int kmap[9] = {0, 3, 5,  1, -1, 6,  2, 4, 7};
        if (ij == 4) {
            float ssum = 0.f;
            #pragma unroll
            for (int q = 0; q < 8; q++) ssum += Wm[o * 24 + q * 3 + c];
            wv = -ssum;
        } else {
            wv = Wm[o * 24 + kmap[ij] * 3 + c];
        }
    }
    g_wB[k * 32 + o] = cvt_tf32(wv);
}

__device__ __forceinline__ float lds_f32(uint32_t addr) {
    float v;
    asm volatile("ld.shared.f32 %0, [%1];" : "=f"(v) : "r"(addr));
    return v;
}

__device__ __forceinline__ void mma_tf32(float* c, uint32_t a0, uint32_t a1,
                                         uint32_t a2, uint32_t a3,
                                         uint32_t b0, uint32_t b1) {
    asm volatile(
        "mma.sync.aligned.m16n8k8.row.col.f32.tf32.tf32.f32 "
        "{%0,%1,%2,%3}, {%4,%5,%6,%7}, {%8,%9}, {%0,%1,%2,%3};"
        : "+f"(c[0]), "+f"(c[1]), "+f"(c[2]), "+f"(c[3])
        : "r"(a0), "r"(a1), "r"(a2), "r"(a3), "r"(b0), "r"(b1));
}

__global__ __launch_bounds__(NTHREADS, 5)
void pconv_mma_kernel(const float* __restrict__ x,
                      const float* __restrict__ bias,
                      float* __restrict__ out)
{
    __shared__ float xs[XS_FLOATS];
    __shared__ __align__(16) float obuf[4 * BUF_PER_WARP];

    const int tid  = threadIdx.x;
    const int lane = tid & 31;
    const int hr   = tid >> 5;      // warp id = output row within tile
    const int g    = lane >> 2;     // groupID
    const int tig  = lane & 3;      // thread-in-group

    const int w0 = blockIdx.x * 128;
    const int h0 = blockIdx.y * 4;
    const int b  = blockIdx.z;

    // ---- x tile load: 3 ch x 6 rows x 130 cols, zero halo ----
    const float* xb = x + (size_t)b * CIN * HW;
    {
        const int gw  = w0 + tid - 1;
        const bool okw = (unsigned)gw < W_DIM;
        const int gw2 = w0 + tid + (NTHREADS - 1);
        const bool okw2 = (tid < 2) && ((unsigned)gw2 < W_DIM);
        #pragma unroll
        for (int c = 0; c < CIN; c++) {
            const float* pc = xb + (size_t)c * HW;
            #pragma unroll
            for (int r = 0; r < 6; r++) {
                const int gh = h0 + r - 1;
                const bool okh = (unsigned)gh < H_DIM;
                float v = 0.f;
                if (okh && okw) v = pc[gh * W_DIM + gw];
                xs[c * CSTRIDE + r * RSTRIDE + tid] = v;
                float v2 = 0.f;
                if (okh && okw2) v2 = pc[gh * W_DIM + gw2];
                if (tid < 2) xs[c * CSTRIDE + r * RSTRIDE + NTHREADS + tid] = v2;
            }
        }
    }

    // ---- B fragments (weights), held in registers ----
    uint32_t Bf[4][4][2];
    #pragma unroll
    for (int nt = 0; nt < 4; nt++)
        #pragma unroll
        for (int ks = 0; ks < 4; ks++) {
            Bf[nt][ks][0] = g_wB[(8 * ks + tig) * 32 + nt * 8 + g];
            Bf[nt][ks][1] = g_wB[(8 * ks + 4 + tig) * 32 + nt * 8 + g];
        }

    // ---- bias for this thread's output columns ----
    float bias0[4], bias1[4];
    #pragma unroll
    for (int nt = 0; nt < 4; nt++) {
        bias0[nt] = bias[nt * 8 + tig * 2];
        bias1[nt] = bias[nt * 8 + tig * 2 + 1];
    }

    // ---- A-fragment smem addresses (byte), one per (ks, pair) ----
    uint32_t sbase;
    asm("{ .reg .u64 t; cvta.to.shared.u64 t, %1; cvt.u32.u64 %0, t; }"
        : "=r"(sbase) : "l"(xs));
    uint32_t aaddr[8];
    #pragma unroll
    for (int ks = 0; ks < 4; ks++) {
        #pragma unroll
        for (int p = 0; p < 2; p++) {
            const int k = 8 * ks + 4 * p + tig;
            aaddr[ks * 2 + p] = sbase + 4 * (c_OFFS[k] + hr * RSTRIDE + g);
        }
    }

    // ---- epilogue addressing ----
    float* bw = obuf + hr * BUF_PER_WARP;
    const int chsub = lane >> 3;         // 0..3: channel within cc-group of 4
    const int px4   = 4 * (lane & 7);    // 0..28: pixel quad within 32-px row
    float* p0 = out + (size_t)b * COUT * HW + (size_t)chsub * HW
                    + (size_t)(h0 + hr) * W_DIM + w0 + px4;

    __syncthreads();

    // ---- 4 double-tiles of 32 pixels along w ----
    #pragma unroll 1
    for (int dt = 0; dt < 4; dt++) {
        #pragma unroll
        for (int tt = 0; tt < 2; tt++) {
            float acc[4][4];
            #pragma unroll
            for (int nt = 0; nt < 4; nt++) {
                acc[nt][0] = bias0[nt];
                acc[nt][1] = bias1[nt];
                acc[nt][2] = bias0[nt];
                acc[nt][3] = bias1[nt];
            }

            #pragma unroll
            for (int ks = 0; ks < 4; ks++) {
                const uint32_t a0 = cvt_tf32(lds_f32(aaddr[ks * 2]));
                const uint32_t a1 = cvt_tf32(lds_f32(aaddr[ks * 2] + 32));
                const uint32_t a2 = cvt_tf32(lds_f32(aaddr[ks * 2 + 1]));
                const uint32_t a3 = cvt_tf32(lds_f32(aaddr[ks * 2 + 1] + 32));
                #pragma unroll
                for (int nt = 0; nt < 4; nt++)
                    mma_tf32(acc[nt], a0, a1, a2, a3, Bf[nt][ks][0], Bf[nt][ks][1]);
            }

            // stage to smem: buf[ch][px], stride 36 -> conflict-free
            #pragma unroll
            for (int nt = 0; nt < 4; nt++) {
                float* q = bw + (8 * nt + 2 * tig) * BUFW + 16 * tt + g;
                q[0]        = acc[nt][0];
                q[BUFW]     = acc[nt][1];
                q[8]        = acc[nt][2];
                q[BUFW + 8] = acc[nt][3];
            }

            #pragma unroll
            for (int q = 0; q < 8; q++) aaddr[q] += 64;
        }

        __syncwarp();

        // coalesced store: each 8-lane group emits one full 128B out line.
        // 8 cc-iterations x 4 lane-groups = all 32 channels.
        #pragma unroll
        for (int cc = 0; cc < 8; cc++) {
            const float4 v = *(const float4*)&bw[(4 * cc + chsub) * BUFW + px4];
            __stcs((float4*)(p0 + (size_t)(4 * cc) * HW + dt * 32), v);
        }

        __syncwarp();
    }
}

extern "C" void kernel_launch(void* const* d_in, const int* in_sizes, int n_in,
                              void* d_out, int out_size)
{
    const float* x  = (const float*)d_in[0];  // [16,3,512,512]
    const float* Wm = (const float*)d_in[1];  // [32,24]
    const float* bi = (const float*)d_in[2];  // [32]
    float* out = (float*)d_out;               // [16,32,512,512]

    prep_weights_kernel<<<8, 128>>>(Wm);

    dim3 block(NTHREADS, 1, 1);
    dim3 grid(W_DIM / 128, H_DIM / 4, NB);    // (4, 128, 16)
    pconv_mma_kernel<<<grid, block>>>(x, bi, out);
}

// round 13
// speedup vs baseline: 1.0850x; 1.0850x over previous
#include <cuda_runtime.h>
#include <cstdint>

#define H_DIM 512
#define W_DIM 512
#define CIN   3
#define COUT  32
#define NB    16
#define HW    (H_DIM * W_DIM)

#define NTHREADS 128
// smem x-tile layout: xs[c*824 + r*136 + s], c<3, r<6, s<130
#define RSTRIDE 136
#define CSTRIDE 824
#define XS_FLOATS 2496

// output staging buffer: per warp, 32 channels x 32 px, stride 36 (conflict-free)
#define BUFW 36
#define BUF_PER_WARP (32 * BUFW)   // 1152 floats

// Prepped B matrix: g_wB[k*32 + o] = tf32(Weff[o][PERM[k]]), 0 for pad taps
__device__ uint32_t g_wB[32 * 32];

// k -> tap id (c*9+i*3+j); -1 = pad (weight forced to 0).
__device__ __constant__ int c_PERM[32] = {
    0, 3, 6, 9,   12, 15, 18, 21,
    1, 4, 7, 10,  13, 16, 19, 22,
    2, 5, 8, 11,  14, 17, 20, 23,
    24, 25, 26, -1,  -1, -1, -1, -1
};

// smem float-offset for each k (c*824 + i*136 + j).
// Pad taps -> offset 0 (their B weight is exactly 0.0f; tile data is finite).
__device__ __constant__ int c_OFFS[32] = {
    0, 136, 272, 824,    960, 1096, 1648, 1784,
    1, 137, 273, 825,    961, 1097, 1649, 1785,
    2, 138, 274, 826,    962, 1098, 1650, 1786,
    1920, 1921, 1922, 0,  0, 0, 0, 0
};

__device__ __forceinline__ uint32_t cvt_tf32(float f) {
    uint32_t u;
    asm("cvt.rna.tf32.f32 %0, %1;" : "=r"(u) : "f"(f));
    return u;
}

// ---- one-time weight prep ----
__global__ void prep_weights_kernel(const float* __restrict__ Wm)
{
    const int s = blockIdx.x * blockDim.x + threadIdx.x;
    if (s >= 32 * 32) return;
    const int k = s / 32;
    const int o = s % 32;
    const int tap = c_PERM[k];
    float wv = 0.f;
    if (tap >= 0) {
        const int c  = tap / 9;
        const int ij = tap % 9;
        // COORDS order for ij=(i*3+j): (0,0),(1,0),(2,0),(0,1),(2,1),(0,2),(1,2),(2,2)
        const int kmap[9] = {0, 3, 5,  1, -1, 6,  2, 4, 7};
        if (ij == 4) {
            float ssum = 0.f;
            #pragma unroll
            for (int q = 0; q < 8; q++) ssum += Wm[o * 24 + q * 3 + c];
            wv = -ssum;
        } else {
            wv = Wm[o * 24 + kmap[ij] * 3 + c];
        }
    }
    g_wB[k * 32 + o] = cvt_tf32(wv);
}

__device__ __forceinline__ float lds_f32(uint32_t addr) {
    float v;
    asm volatile("ld.shared.f32 %0, [%1];" : "=f"(v) : "r"(addr));
    return v;
}

__device__ __forceinline__ void mma_tf32(float* c, uint32_t a0, uint32_t a1,
                                         uint32_t a2, uint32_t a3,
                                         uint32_t b0, uint32_t b1) {
    asm volatile(
        "mma.sync.aligned.m16n8k8.row.col.f32.tf32.tf32.f32 "
        "{%0,%1,%2,%3}, {%4,%5,%6,%7}, {%8,%9}, {%0,%1,%2,%3};"
        : "+f"(c[0]), "+f"(c[1]), "+f"(c[2]), "+f"(c[3])
        : "r"(a0), "r"(a1), "r"(a2), "r"(a3), "r"(b0), "r"(b1));
}

__global__ __launch_bounds__(NTHREADS, 6)
void pconv_mma_kernel(const float* __restrict__ x,
                      const float* __restrict__ bias,
                      float* __restrict__ out)
{
    __shared__ float xs[XS_FLOATS];
    __shared__ __align__(16) float obuf[4 * BUF_PER_WARP];

    const int tid  = threadIdx.x;
    const int lane = tid & 31;
    const int hr   = tid >> 5;      // warp id = output row within tile
    const int g    = lane >> 2;     // groupID
    const int tig  = lane & 3;      // thread-in-group

    const int w0 = blockIdx.x * 128;
    const int h0 = blockIdx.y * 4;
    const int b  = blockIdx.z;

    // ---- x tile load: 3 ch x 6 rows x 130 cols, zero halo ----
    const float* xb = x + (size_t)b * CIN * HW;
    {
        const int gw  = w0 + tid - 1;
        const bool okw = (unsigned)gw < W_DIM;
        const int gw2 = w0 + tid + (NTHREADS - 1);
        const bool okw2 = (tid < 2) && ((unsigned)gw2 < W_DIM);
        #pragma unroll
        for (int c = 0; c < CIN; c++) {
            const float* pc = xb + (size_t)c * HW;
            #pragma unroll
            for (int r = 0; r < 6; r++) {
                const int gh = h0 + r - 1;
                const bool okh = (unsigned)gh < H_DIM;
                float v = 0.f;
                if (okh && okw) v = pc[gh * W_DIM + gw];
                xs[c * CSTRIDE + r * RSTRIDE + tid] = v;
                float v2 = 0.f;
                if (okh && okw2) v2 = pc[gh * W_DIM + gw2];
                if (tid < 2) xs[c * CSTRIDE + r * RSTRIDE + NTHREADS + tid] = v2;
            }
        }
    }

    // ---- B fragments (weights), held in registers ----
    uint32_t Bf[4][4][2];
    #pragma unroll
    for (int nt = 0; nt < 4; nt++)
        #pragma unroll
        for (int ks = 0; ks < 4; ks++) {
            Bf[nt][ks][0] = g_wB[(8 * ks + tig) * 32 + nt * 8 + g];
            Bf[nt][ks][1] = g_wB[(8 * ks + 4 + tig) * 32 + nt * 8 + g];
        }

    // ---- bias for this thread's output columns ----
    float bias0[4], bias1[4];
    #pragma unroll
    for (int nt = 0; nt < 4; nt++) {
        bias0[nt] = bias[nt * 8 + tig * 2];
        bias1[nt] = bias[nt * 8 + tig * 2 + 1];
    }

    // ---- A-fragment smem addresses (byte), one per (ks, pair) ----
    uint32_t sbase;
    asm("{ .reg .u64 t; cvta.to.shared.u64 t, %1; cvt.u32.u64 %0, t; }"
        : "=r"(sbase) : "l"(xs));
    uint32_t aaddr[8];
    #pragma unroll
    for (int ks = 0; ks < 4; ks++) {
        #pragma unroll
        for (int p = 0; p < 2; p++) {
            const int k = 8 * ks + 4 * p + tig;
            aaddr[ks * 2 + p] = sbase + 4 * (c_OFFS[k] + hr * RSTRIDE + g);
        }
    }

    // ---- epilogue addressing: single base pointer, offsets fold to constants ----
    float* bw = obuf + hr * BUF_PER_WARP;
    const int chsub = lane >> 3;         // 0..3: channel within cc-group of 4
    const int px4   = 4 * (lane & 7);    // 0..28: pixel quad within 32-px row
    float* p0 = out + (size_t)b * COUT * HW + (size_t)chsub * HW
                    + (size_t)(h0 + hr) * W_DIM + w0 + px4;

    __syncthreads();

    // ---- 4 double-tiles of 32 pixels along w ----
    #pragma unroll 1
    for (int dt = 0; dt < 4; dt++) {
        #pragma unroll
        for (int tt = 0; tt < 2; tt++) {
            float acc[4][4];
            #pragma unroll
            for (int nt = 0; nt < 4; nt++) {
                acc[nt][0] = bias0[nt];
                acc[nt][1] = bias1[nt];
                acc[nt][2] = bias0[nt];
                acc[nt][3] = bias1[nt];
            }

            #pragma unroll
            for (int ks = 0; ks < 4; ks++) {
                const uint32_t a0 = cvt_tf32(lds_f32(aaddr[ks * 2]));
                const uint32_t a1 = cvt_tf32(lds_f32(aaddr[ks * 2] + 32));
                const uint32_t a2 = cvt_tf32(lds_f32(aaddr[ks * 2 + 1]));
                const uint32_t a3 = cvt_tf32(lds_f32(aaddr[ks * 2 + 1] + 32));
                #pragma unroll
                for (int nt = 0; nt < 4; nt++)
                    mma_tf32(acc[nt], a0, a1, a2, a3, Bf[nt][ks][0], Bf[nt][ks][1]);
            }

            // stage to smem: buf[ch][px], stride 36 -> conflict-free
            #pragma unroll
            for (int nt = 0; nt < 4; nt++) {
                float* q = bw + (8 * nt + 2 * tig) * BUFW + 16 * tt + g;
                q[0]        = acc[nt][0];
                q[BUFW]     = acc[nt][1];
                q[8]        = acc[nt][2];
                q[BUFW + 8] = acc[nt][3];
            }

            #pragma unroll
            for (int q = 0; q < 8; q++) aaddr[q] += 64;
        }

        __syncwarp();

        // coalesced store: each 8-lane group emits one full 128B out line.
        // 8 cc-iterations x 4 lane-groups = all 32 channels.
        #pragma unroll
        for (int cc = 0; cc < 8; cc++) {
            const float4 v = *(const float4*)&bw[(4 * cc + chsub) * BUFW + px4];
            __stcs((float4*)(p0 + (size_t)cc * (4 * HW) + dt * 32), v);
        }

        __syncwarp();
    }
}

extern "C" void kernel_launch(void* const* d_in, const int* in_sizes, int n_in,
                              void* d_out, int out_size)
{
    const float* x  = (const float*)d_in[0];  // [16,3,512,512]
    const float* Wm = (const float*)d_in[1];  // [32,24]
    const float* bi = (const float*)d_in[2];  // [32]
    float* out = (float*)d_out;               // [16,32,512,512]

    prep_weights_kernel<<<8, 128>>>(Wm);

    dim3 block(NTHREADS, 1, 1);
    dim3 grid(W_DIM / 128, H_DIM / 4, NB);    // (4, 128, 16)
    pconv_mma_kernel<<<grid, block>>>(x, bi, out);
}

// round 15
// speedup vs baseline: 1.1285x; 1.0401x over previous
#include <cuda_runtime.h>
#include <cstdint>

#define H_DIM 512
#define W_DIM 512
#define CIN   3
#define COUT  32
#define NB    16
#define HW    (H_DIM * W_DIM)

#define NTHREADS 128
// smem x-tile layout: xs[c*824 + r*136 + s], c<3, r<6, s<130
#define RSTRIDE 136
#define CSTRIDE 824
#define XS_FLOATS 2496

// output staging buffer: per warp, 32 channels x 32 px, stride 36 (conflict-free)
#define BUFW 36
#define BUF_PER_WARP (32 * BUFW)   // 1152 floats

// Prepped B matrix: g_wB[k*32 + o] = tf32(Weff[o][PERM[k]]), 0 for pad taps
__device__ uint32_t g_wB[32 * 32];

// k -> tap id (c*9+i*3+j); -1 = pad (weight forced to 0).
__device__ __constant__ int c_PERM[32] = {
    0, 3, 6, 9,   12, 15, 18, 21,
    1, 4, 7, 10,  13, 16, 19, 22,
    2, 5, 8, 11,  14, 17, 20, 23,
    24, 25, 26, -1,  -1, -1, -1, -1
};

// smem float-offset for each k (c*824 + i*136 + j).
// Row structure exploited in-kernel: offs[8+k']=offs[k']+1, offs[16+k']=offs[k']+2
// (so ks1/ks2 A-addresses = ks0 address + 4/+8 bytes). Pad taps -> offset 0.
__device__ __constant__ int c_OFFS[32] = {
    0, 136, 272, 824,    960, 1096, 1648, 1784,
    1, 137, 273, 825,    961, 1097, 1649, 1785,
    2, 138, 274, 826,    962, 1098, 1650, 1786,
    1920, 1921, 1922, 0,  0, 0, 0, 0
};

__device__ __forceinline__ uint32_t cvt_tf32(float f) {
    uint32_t u;
    asm("cvt.rna.tf32.f32 %0, %1;" : "=r"(u) : "f"(f));
    return u;
}

// ---- one-time weight prep ----
__global__ void prep_weights_kernel(const float* __restrict__ Wm)
{
    const int s = blockIdx.x * blockDim.x + threadIdx.x;
    if (s >= 32 * 32) return;
    const int k = s / 32;
    const int o = s % 32;
    const int tap = c_PERM[k];
    float wv = 0.f;
    if (tap >= 0) {
        const int c  = tap / 9;
        const int ij = tap % 9;
        // COORDS order for ij=(i*3+j): (0,0),(1,0),(2,0),(0,1),(2,1),(0,2),(1,2),(2,2)
        const int kmap[9] = {0, 3, 5,  1, -1, 6,  2, 4, 7};
        if (ij == 4) {
            float ssum = 0.f;
            #pragma unroll
            for (int q = 0; q < 8; q++) ssum += Wm[o * 24 + q * 3 + c];
            wv = -ssum;
        } else {
            wv = Wm[o * 24 + kmap[ij] * 3 + c];
        }
    }
    g_wB[k * 32 + o] = cvt_tf32(wv);
}

__device__ __forceinline__ float lds_f32(uint32_t addr) {
    float v;
    asm volatile("ld.shared.f32 %0, [%1];" : "=f"(v) : "r"(addr));
    return v;
}

__device__ __forceinline__ void mma_tf32(float* c, uint32_t a0, uint32_t a1,
                                         uint32_t a2, uint32_t a3,
                                         uint32_t b0, uint32_t b1) {
    asm volatile(
        "mma.sync.aligned.m16n8k8.row.col.f32.tf32.tf32.f32 "
        "{%0,%1,%2,%3}, {%4,%5,%6,%7}, {%8,%9}, {%0,%1,%2,%3};"
        : "+f"(c[0]), "+f"(c[1]), "+f"(c[2]), "+f"(c[3])
        : "r"(a0), "r"(a1), "r"(a2), "r"(a3), "r"(b0), "r"(b1));
}

__global__ __launch_bounds__(NTHREADS, 7)
void pconv_mma_kernel(const float* __restrict__ x,
                      const float* __restrict__ bias,
                      float* __restrict__ out)
{
    __shared__ float xs[XS_FLOATS];
    __shared__ __align__(16) float obuf[4 * BUF_PER_WARP];

    const int tid  = threadIdx.x;
    const int lane = tid & 31;
    const int hr   = tid >> 5;      // warp id = output row within tile
    const int g    = lane >> 2;     // groupID
    const int tig  = lane & 3;      // thread-in-group

    const int w0 = blockIdx.x * 128;
    const int h0 = blockIdx.y * 4;
    const int b  = blockIdx.z;

    // ---- x tile load: 3 ch x 6 rows x 130 cols, zero halo ----
    const float* xb = x + (size_t)b * CIN * HW;
    {
        const int gw  = w0 + tid - 1;
        const bool okw = (unsigned)gw < W_DIM;
        const int gw2 = w0 + tid + (NTHREADS - 1);
        const bool okw2 = (tid < 2) && ((unsigned)gw2 < W_DIM);
        #pragma unroll
        for (int c = 0; c < CIN; c++) {
            const float* pc = xb + (size_t)c * HW;
            #pragma unroll
            for (int r = 0; r < 6; r++) {
                const int gh = h0 + r - 1;
                const bool okh = (unsigned)gh < H_DIM;
                float v = 0.f;
                if (okh && okw) v = pc[gh * W_DIM + gw];
                xs[c * CSTRIDE + r * RSTRIDE + tid] = v;
                float v2 = 0.f;
                if (okh && okw2) v2 = pc[gh * W_DIM + gw2];
                if (tid < 2) xs[c * CSTRIDE + r * RSTRIDE + NTHREADS + tid] = v2;
            }
        }
    }

    // ---- B fragments (weights), held in registers ----
    // Bf1[nt][3] would cover k=28..31: all pads, all zero -> dropped entirely.
    uint32_t Bf0[4][4], Bf1[4][3];
    #pragma unroll
    for (int nt = 0; nt < 4; nt++) {
        #pragma unroll
        for (int ks = 0; ks < 4; ks++)
            Bf0[nt][ks] = g_wB[(8 * ks + tig) * 32 + nt * 8 + g];
        #pragma unroll
        for (int ks = 0; ks < 3; ks++)
            Bf1[nt][ks] = g_wB[(8 * ks + 4 + tig) * 32 + nt * 8 + g];
    }

    // ---- bias for this thread's output columns ----
    float bias0[4], bias1[4];
    #pragma unroll
    for (int nt = 0; nt < 4; nt++) {
        bias0[nt] = bias[nt * 8 + tig * 2];
        bias1[nt] = bias[nt * 8 + tig * 2 + 1];
    }

    // ---- A-fragment smem base addresses (byte): 3 regs, rest fold to imms ----
    uint32_t sbase;
    asm("{ .reg .u64 t; cvta.to.shared.u64 t, %1; cvt.u32.u64 %0, t; }"
        : "=r"(sbase) : "l"(xs));
    const uint32_t lin = hr * RSTRIDE + g;
    uint32_t aA = sbase + 4 * (c_OFFS[tig]      + lin);  // ks0..2, p0 (+4*ks bytes)
    uint32_t aB = sbase + 4 * (c_OFFS[4 + tig]  + lin);  // ks0..2, p1 (+4*ks bytes)
    uint32_t aC = sbase + 4 * (c_OFFS[24 + tig] + lin);  // ks3, p0

    // ---- epilogue addressing ----
    float* bw = obuf + hr * BUF_PER_WARP;
    const int chsub = lane >> 3;         // 0..3: channel within cc-group of 4
    const int px4   = 4 * (lane & 7);    // 0..28: pixel quad within 32-px row
    float* p0 = out + (size_t)b * COUT * HW + (size_t)chsub * HW
                    + (size_t)(h0 + hr) * W_DIM + w0 + px4;

    __syncthreads();

    // ---- 4 double-tiles of 32 pixels along w ----
    #pragma unroll 1
    for (int dt = 0; dt < 4; dt++) {
        #pragma unroll
        for (int tt = 0; tt < 2; tt++) {
            float acc[4][4];
            #pragma unroll
            for (int nt = 0; nt < 4; nt++) {
                acc[nt][0] = bias0[nt];
                acc[nt][1] = bias1[nt];
                acc[nt][2] = bias0[nt];
                acc[nt][3] = bias1[nt];
            }

            // ks 0..2: addresses aA/aB + 4*ks (immediate offsets).
            // Row+8 fragment element (pixel g+8) is +32 BYTES (+8 floats).
            #pragma unroll
            for (int ks = 0; ks < 3; ks++) {
                const uint32_t a0 = cvt_tf32(lds_f32(aA + 4 * ks));
                const uint32_t a1 = cvt_tf32(lds_f32(aA + 4 * ks + 32));
                const uint32_t a2 = cvt_tf32(lds_f32(aB + 4 * ks));
                const uint32_t a3 = cvt_tf32(lds_f32(aB + 4 * ks + 32));
                #pragma unroll
                for (int nt = 0; nt < 4; nt++)
                    mma_tf32(acc[nt], a0, a1, a2, a3, Bf0[nt][ks], Bf1[nt][ks]);
            }
            // ks 3: b1 half is all-zero -> skip a2/a3 loads entirely
            {
                const uint32_t a0 = cvt_tf32(lds_f32(aC));
                const uint32_t a1 = cvt_tf32(lds_f32(aC + 32));
                #pragma unroll
                for (int nt = 0; nt < 4; nt++)
                    mma_tf32(acc[nt], a0, a1, 0u, 0u, Bf0[nt][3], 0u);
            }

            // stage to smem: buf[ch][px], stride 36 -> conflict-free
            #pragma unroll
            for (int nt = 0; nt < 4; nt++) {
                float* q = bw + (8 * nt + 2 * tig) * BUFW + 16 * tt + g;
                q[0]        = acc[nt][0];
                q[BUFW]     = acc[nt][1];
                q[8]        = acc[nt][2];
                q[BUFW + 8] = acc[nt][3];
            }

            aA += 64; aB += 64; aC += 64;
        }

        __syncwarp();

        // coalesced store: each 8-lane group emits one full 128B out line.
        // 8 cc-iterations x 4 lane-groups = all 32 channels.
        #pragma unroll
        for (int cc = 0; cc < 8; cc++) {
            const float4 v = *(const float4*)&bw[(4 * cc + chsub) * BUFW + px4];
            __stcs((float4*)(p0 + (size_t)cc * (4 * HW) + dt * 32), v);
        }

        __syncwarp();
    }
}

extern "C" void kernel_launch(void* const* d_in, const int* in_sizes, int n_in,
                              void* d_out, int out_size)
{
    const float* x  = (const float*)d_in[0];  // [16,3,512,512]
    const float* Wm = (const float*)d_in[1];  // [32,24]
    const float* bi = (const float*)d_in[2];  // [32]
    float* out = (float*)d_out;               // [16,32,512,512]

    prep_weights_kernel<<<8, 128>>>(Wm);

    dim3 block(NTHREADS, 1, 1);
    dim3 grid(W_DIM / 128, H_DIM / 4, NB);    // (4, 128, 16)
    pconv_mma_kernel<<<grid, block>>>(x, bi, out);
}